// round 7
// baseline (speedup 1.0000x reference)
#include <cuda_runtime.h>
#include <math.h>
#include <stdint.h>

#define NNODE 512
#define MEMD  512
#define NIOU  1536
#define NCOMB 2048
#define NPAD  513   // row 512 = permanent zero (padded child)
#define GRIDB 148
#define TPB   512
#define SMEMSZ 61440

// Scratch state (device globals: allocation-free rule)
__device__ float g_xiouf[2 * NNODE * NCOMB];  // [xiou(1536) | xf(512)] per node, biases included
__device__ float g_ziou[2 * NNODE * NIOU];    // (sum_children h) @ W_iouh, internal (j>=384) only
__device__ float g_y[2 * NPAD * MEMD];        // h @ W_fh per node (+ pad zero row)
__device__ float g_c[2 * NPAD * MEMD];
__device__ float g_h[2 * NPAD * MEMD];
__device__ float g_part[16 * MEMD];           // head partial sums
__device__ unsigned g_bar;                    // software grid barrier counter

__constant__ int c_j0s[6]  = {0, 171, 427, 491, 507, 511};
__constant__ int c_cnt[6]  = {171, 256, 64, 16, 4, 1};
__constant__ int c_j0i[5]  = {384, 427, 491, 507, 511};
__constant__ int c_cnti[5] = {43, 64, 16, 4, 1};

__device__ __forceinline__ float sigm(float x) { return 1.f / (1.f + __expf(-x)); }
__device__ __forceinline__ float4 ld4(const float* p) { return *(const float4*)p; }
__device__ __forceinline__ float4 f4add(float4 a, float4 b) {
    return make_float4(a.x + b.x, a.y + b.y, a.z + b.z, a.w + b.w);
}
__device__ __forceinline__ uint32_t to_tf32(float x) {
    uint32_t r; asm("cvt.rna.tf32.f32 %0, %1;" : "=r"(r) : "f"(x)); return r;
}
__device__ __forceinline__ uint4 cvt4(float4 v) {
    uint4 r; r.x = to_tf32(v.x); r.y = to_tf32(v.y); r.z = to_tf32(v.z); r.w = to_tf32(v.w);
    return r;
}
__device__ __forceinline__ void mma_tf32(float d[4], const uint32_t a[4], const uint32_t b[2]) {
    asm volatile(
        "mma.sync.aligned.m16n8k8.row.col.f32.tf32.tf32.f32 "
        "{%0,%1,%2,%3}, {%4,%5,%6,%7}, {%8,%9}, {%0,%1,%2,%3};"
        : "+f"(d[0]), "+f"(d[1]), "+f"(d[2]), "+f"(d[3])
        : "r"(a[0]), "r"(a[1]), "r"(a[2]), "r"(a[3]), "r"(b[0]), "r"(b[1]));
}

#define HBAR(b) asm volatile("bar.sync %0, 256;" :: "r"(b) : "memory")

// Software grid barrier. Counter is monotonic within one kernel run; reset by k_zero.
__device__ __forceinline__ void gsync(unsigned target) {
    __syncthreads();
    if (threadIdx.x == 0) {
        __threadfence();
        atomicAdd(&g_bar, 1u);
        while (*(volatile unsigned*)&g_bar < target) {}
        __threadfence();
    }
    __syncthreads();
}

// Reset barrier counter + permanent pad rows (fresh every call -> graph replays deterministic).
__global__ void k_zero() {
    int tid = threadIdx.x;  // 0..511
    if (tid == 0) g_bar = 0;
#pragma unroll
    for (int t = 0; t < 2; t++) {
        g_y[(size_t)(t * NPAD + NNODE) * MEMD + tid] = 0.f;
        g_c[(size_t)(t * NPAD + NNODE) * MEMD + tid] = 0.f;
        g_h[(size_t)(t * NPAD + NNODE) * MEMD + tid] = 0.f;
    }
}

// One 32(M)x64(N)xK512 tf32 GEMM tile, run by a 256-thread half-block (named barrier nbar).
// As: [2][32][40], Bs: [2][32][72] (double-buffered, conflict-free strides = 8 mod 32).
__device__ __forceinline__ void gemm32x64(
    int htid, int nbar,
    uint32_t (*As)[32][40], uint32_t (*Bs)[32][72],
    const float* a0, const float* a1, const float* a2, const float* a3,
    bool avalid, bool sum4,
    const float* __restrict__ Bsrc, int bld,
    const float* __restrict__ bias,
    float* cbase, int cld, int Plim)
{
    const int arow = htid >> 3, acol = (htid & 7) << 2;
    const int brow = htid >> 4, bc4 = (htid & 15) << 2;
    const int lane = htid & 31, wid = htid >> 5;
    const int wm = (wid & 1) * 16, wn = (wid >> 1) * 16;
    const int g = lane >> 2, tg = lane & 3;
    float acc[2][4] = {};

    {
        float4 av = make_float4(0.f, 0.f, 0.f, 0.f);
        if (avalid) {
            av = ld4(a0);
            if (sum4) av = f4add(f4add(av, ld4(a1)), f4add(ld4(a2), ld4(a3)));
        }
        *(uint4*)&As[0][arow][acol]     = cvt4(av);
        *(uint4*)&Bs[0][brow][bc4]      = cvt4(ld4(Bsrc + (size_t)brow * bld + bc4));
        *(uint4*)&Bs[0][brow + 16][bc4] = cvt4(ld4(Bsrc + (size_t)(brow + 16) * bld + bc4));
    }
    HBAR(nbar);

    int cur = 0;
    for (int it = 0; it < 16; it++) {
        float4 an = make_float4(0.f, 0.f, 0.f, 0.f), bn0, bn1;
        if (it < 15) {
            int k0 = (it + 1) * 32;
            if (avalid) {
                an = ld4(a0 + k0);
                if (sum4) an = f4add(f4add(an, ld4(a1 + k0)), f4add(ld4(a2 + k0), ld4(a3 + k0)));
            }
            bn0 = ld4(Bsrc + (size_t)(k0 + brow) * bld + bc4);
            bn1 = ld4(Bsrc + (size_t)(k0 + brow + 16) * bld + bc4);
        }
#pragma unroll
        for (int kk = 0; kk < 32; kk += 8) {
            uint32_t af[4], bf[2][2];
            af[0] = As[cur][wm + g][kk + tg];
            af[1] = As[cur][wm + g + 8][kk + tg];
            af[2] = As[cur][wm + g][kk + tg + 4];
            af[3] = As[cur][wm + g + 8][kk + tg + 4];
#pragma unroll
            for (int j = 0; j < 2; j++) {
                int bc = wn + j * 8 + g;
                bf[j][0] = Bs[cur][kk + tg][bc];
                bf[j][1] = Bs[cur][kk + tg + 4][bc];
            }
            mma_tf32(acc[0], af, bf[0]);
            mma_tf32(acc[1], af, bf[1]);
        }
        if (it < 15) {
            int nxt = cur ^ 1;
            *(uint4*)&As[nxt][arow][acol]     = cvt4(an);
            *(uint4*)&Bs[nxt][brow][bc4]      = cvt4(bn0);
            *(uint4*)&Bs[nxt][brow + 16][bc4] = cvt4(bn1);
            HBAR(nbar);
            cur = nxt;
        }
    }

#pragma unroll
    for (int j = 0; j < 2; j++) {
        int colin = wn + j * 8 + 2 * tg;
#pragma unroll
        for (int r = 0; r < 2; r++) {
            int mrow = wm + g + r * 8;
            if (mrow < Plim) {
                float2 v = make_float2(acc[j][2 * r], acc[j][2 * r + 1]);
                if (bias) { v.x += bias[colin]; v.y += bias[colin + 1]; }
                *(float2*)(cbase + (size_t)mrow * cld + colin) = v;
            }
        }
    }
}

// Persistent kernel: all phases in one launch, separated by software grid barriers.
__global__ __launch_bounds__(TPB) void k_all(
    const int* __restrict__ linp, const int* __restrict__ rinp,
    const int* __restrict__ lch, const int* __restrict__ rch,
    const float* __restrict__ emb,
    const float* __restrict__ Wioux, const float* __restrict__ bioux,
    const float* __restrict__ Wiouh, const float* __restrict__ biouh,
    const float* __restrict__ Wfx, const float* __restrict__ bfx,
    const float* __restrict__ Wfh, const float* __restrict__ bfh,
    const float* __restrict__ Wh, const float* __restrict__ bh,
    const float* __restrict__ Wp, const float* __restrict__ bp,
    float* __restrict__ out)
{
    extern __shared__ unsigned char smem_raw[];
    uint32_t (*AsAll)[2][32][40] = reinterpret_cast<uint32_t (*)[2][32][40]>(smem_raw);
    uint32_t (*BsAll)[2][32][72] = reinterpret_cast<uint32_t (*)[2][32][72]>(smem_raw + 20480);
    float* sh_hid = (float*)(smem_raw + 57344);
    float* sh_vec = sh_hid + 512;
    float* sh_logit = sh_vec + 64;

    const int tid  = threadIdx.x;
    const int half = tid >> 8;       // two 256-thread GEMM engines per block
    const int htid = tid & 255;
    const int nbar = 1 + half;       // named barrier id (0 reserved for __syncthreads)
    const int slot = blockIdx.x * 2 + half;
    unsigned gen = 0;

    // ---------------- PRE: g_xiouf = emb[tok] @ [W_ioux|W_fx] + bias  (1024 x 2048) ----------------
    for (int u = slot; u < 1024; u += 2 * GRIDB) {
        int n0 = (u & 31) * 64;
        int m0 = (u >> 5) * 32;
        int arow = htid >> 3, acol = (htid & 7) << 2;
        int gm = m0 + arow;
        int tok = (gm < NNODE) ? linp[gm] : rinp[gm - NNODE];
        const float* a0 = emb + (size_t)tok * MEMD + acol;
        const float* Bsrc; int bld; const float* bias;
        if (n0 < NIOU) { Bsrc = Wioux + n0;          bld = NIOU; bias = bioux + n0; }
        else           { Bsrc = Wfx + (n0 - NIOU);   bld = MEMD; bias = bfx + (n0 - NIOU); }
        gemm32x64(htid, nbar, AsAll[half], BsAll[half], a0, 0, 0, 0, true, false,
                  Bsrc, bld, bias, g_xiouf + (size_t)m0 * NCOMB + n0, NCOMB, 32);
    }
    gen++; gsync(gen * GRIDB);

    // ---------------- Tree levels ----------------
    for (int l = 0; l < 6; l++) {
        // ---- update phase: 128 threads per (node, tree) unit, 4 units per block ----
        {
            int units = c_cnt[l] * 2;
            int utid = tid & 127;
            for (int u = blockIdx.x * 4 + (tid >> 7); u < units; u += GRIDB * 4) {
                int t = u & 1;
                int j = c_j0s[l] + (u >> 1);
                const int* chp = (t ? rch : lch) + j * 4;
                int c0 = chp[0], c1 = chp[1], c2 = chp[2], c3 = chp[3];
                int d = utid << 2;

                const float* x = g_xiouf + (size_t)(t * NNODE + j) * NCOMB;
                float4 Zi, Zo, Zu;
                if (j >= 384) {
                    const float* z = g_ziou + ((size_t)t * NNODE + j) * NIOU;
                    Zi = ld4(z + d); Zo = ld4(z + 512 + d); Zu = ld4(z + 1024 + d);
                } else {
                    Zi = Zo = Zu = make_float4(0.f, 0.f, 0.f, 0.f);
                }
                float4 Y0 = ld4(g_y + (size_t)(t * NPAD + c0) * MEMD + d);
                float4 Y1 = ld4(g_y + (size_t)(t * NPAD + c1) * MEMD + d);
                float4 Y2 = ld4(g_y + (size_t)(t * NPAD + c2) * MEMD + d);
                float4 Y3 = ld4(g_y + (size_t)(t * NPAD + c3) * MEMD + d);
                float4 Cc0 = ld4(g_c + (size_t)(t * NPAD + c0) * MEMD + d);
                float4 Cc1 = ld4(g_c + (size_t)(t * NPAD + c1) * MEMD + d);
                float4 Cc2 = ld4(g_c + (size_t)(t * NPAD + c2) * MEMD + d);
                float4 Cc3 = ld4(g_c + (size_t)(t * NPAD + c3) * MEMD + d);
                float4 Xi = ld4(x + d), Xo = ld4(x + 512 + d), Xu = ld4(x + 1024 + d), Xf = ld4(x + 1536 + d);
                float4 Bi = ld4(biouh + d), Bo = ld4(biouh + 512 + d), Bu = ld4(biouh + 1024 + d), Bf = ld4(bfh + d);

                float4 Oc, Oh;
#define DO(C) { \
    float ig = sigm(Xi.C + Zi.C + Bi.C); \
    float og = sigm(Xo.C + Zo.C + Bo.C); \
    float ug = tanhf(Xu.C + Zu.C + Bu.C); \
    float fb = Xf.C + Bf.C; \
    float c  = ig * ug + sigm(Y0.C + fb) * Cc0.C + sigm(Y1.C + fb) * Cc1.C \
                       + sigm(Y2.C + fb) * Cc2.C + sigm(Y3.C + fb) * Cc3.C; \
    Oc.C = c; Oh.C = og * tanhf(c); }
                DO(x) DO(y) DO(z) DO(w)
#undef DO
                *(float4*)(g_c + (size_t)(t * NPAD + j) * MEMD + d) = Oc;
                *(float4*)(g_h + (size_t)(t * NPAD + j) * MEMD + d) = Oh;
            }
        }
        gen++; gsync(gen * GRIDB);

        // ---- level GEMM phase: stable slot -> weight-strip mapping (L1-hot B across levels) ----
        if (l < 5) {
            int mtf = (c_cnt[l] + 31) >> 5, mti = (c_cnti[l] + 31) >> 5;
            bool active = false, fpart = false;
            int n0 = 0, mtile = 0, t = 0;
            if (slot < 128) {            // f-part: strip = tree*8 + n-strip over W_fh
                fpart = true;
                int strip = slot >> 3; mtile = slot & 7;
                t = strip >> 3; n0 = (strip & 7) * 64;
                active = (mtile < mtf);
            } else if (slot < 224) {     // iou-part: strip = tree*24 + n-strip over W_iouh
                int s2 = slot - 128;
                int strip = s2 >> 1; mtile = s2 & 1;
                t = strip / 24; n0 = (strip % 24) * 64;
                active = (mtile < mti);
            }
            if (active) {
                int arow = htid >> 3, acol = (htid & 7) << 2;
                int gm = mtile * 32 + arow;
                if (fpart) {
                    bool av = (gm < c_cnt[l]);
                    const float* a0 = g_h + (size_t)(t * NPAD + c_j0s[l] + (av ? gm : 0)) * MEMD + acol;
                    gemm32x64(htid, nbar, AsAll[half], BsAll[half], a0, 0, 0, 0, av, false,
                              Wfh + n0, MEMD, 0,
                              g_y + (size_t)(t * NPAD + c_j0s[l] + mtile * 32) * MEMD + n0,
                              MEMD, c_cnt[l] - mtile * 32);
                } else {
                    bool av = (gm < c_cnti[l]);
                    int j = c_j0i[l] + (av ? gm : 0);
                    const int* chp = (t ? rch : lch) + j * 4;
                    const float* a0 = g_h + (size_t)(t * NPAD + chp[0]) * MEMD + acol;
                    const float* a1 = g_h + (size_t)(t * NPAD + chp[1]) * MEMD + acol;
                    const float* a2 = g_h + (size_t)(t * NPAD + chp[2]) * MEMD + acol;
                    const float* a3 = g_h + (size_t)(t * NPAD + chp[3]) * MEMD + acol;
                    gemm32x64(htid, nbar, AsAll[half], BsAll[half], a0, a1, a2, a3, av, true,
                              Wiouh + n0, NIOU, 0,
                              g_ziou + ((size_t)t * NNODE + c_j0i[l] + mtile * 32) * NIOU + n0,
                              NIOU, c_cnti[l] - mtile * 32);
                }
            }
            gen++; gsync(gen * GRIDB);
        }
    }

    // ---------------- head1: partial hid pre-activations ----------------
    if (blockIdx.x < 16) {
        int d0 = blockIdx.x * 64;
        const float* lc = g_c + (size_t)(NNODE - 1) * MEMD;
        const float* rc = g_c + (size_t)(NPAD + NNODE - 1) * MEMD;
        if (tid < 64) {
            int dd = d0 + tid;
            sh_vec[tid] = (dd < 512) ? lc[dd] * rc[dd] : fabsf(lc[dd - 512] - rc[dd - 512]);
        }
        __syncthreads();
        float acc = 0.f;
#pragma unroll 8
        for (int dd = 0; dd < 64; dd++)
            acc += sh_vec[dd] * Wh[(size_t)(d0 + dd) * 512 + tid];
        g_part[blockIdx.x * 512 + tid] = acc;
    }
    gen++; gsync(gen * GRIDB);

    // ---------------- head2: sigmoid + tiny GEMV + log_softmax ----------------
    if (blockIdx.x == 0) {
        float a = 0.f;
#pragma unroll
        for (int b = 0; b < 16; b++) a += g_part[b * 512 + tid];
        sh_hid[tid] = sigm(a + bh[tid]);
        __syncthreads();
        if (tid < 160) {
            int c = tid / 32, lane = tid & 31;
            float s = 0.f;
            for (int o = lane; o < 512; o += 32) s += sh_hid[o] * Wp[o * 5 + c];
#pragma unroll
            for (int off = 16; off; off >>= 1) s += __shfl_down_sync(0xffffffffu, s, off);
            if (lane == 0) sh_logit[c] = s + bp[c];
        }
        __syncthreads();
        if (tid == 0) {
            float m = sh_logit[0];
#pragma unroll
            for (int c = 1; c < 5; c++) m = fmaxf(m, sh_logit[c]);
            float se = 0.f;
#pragma unroll
            for (int c = 0; c < 5; c++) se += expf(sh_logit[c] - m);
            float lse = m + logf(se);
#pragma unroll
            for (int c = 0; c < 5; c++) out[c] = sh_logit[c] - lse;
        }
    }
}

extern "C" void kernel_launch(void* const* d_in, const int* in_sizes, int n_in,
                              void* d_out, int out_size)
{
    const int*   linp  = (const int*)d_in[0];
    const int*   rinp  = (const int*)d_in[1];
    const int*   lch   = (const int*)d_in[2];
    const int*   rch   = (const int*)d_in[3];
    const float* emb   = (const float*)d_in[4];
    const float* Wioux = (const float*)d_in[5];
    const float* bioux = (const float*)d_in[6];
    const float* Wiouh = (const float*)d_in[7];
    const float* biouh = (const float*)d_in[8];
    const float* Wfx   = (const float*)d_in[9];
    const float* bfx   = (const float*)d_in[10];
    const float* Wfh   = (const float*)d_in[11];
    const float* bfh   = (const float*)d_in[12];
    const float* Wh    = (const float*)d_in[13];
    const float* bh    = (const float*)d_in[14];
    const float* Wp    = (const float*)d_in[15];
    const float* bp    = (const float*)d_in[16];
    float* out = (float*)d_out;

    cudaFuncSetAttribute(k_all, cudaFuncAttributeMaxDynamicSharedMemorySize, SMEMSZ);
    k_zero<<<1, 512>>>();
    k_all<<<GRIDB, TPB, SMEMSZ>>>(linp, rinp, lch, rch, emb,
                                  Wioux, bioux, Wiouh, biouh,
                                  Wfx, bfx, Wfh, bfh, Wh, bh, Wp, bp, out);
}

// round 9
// speedup vs baseline: 1.0776x; 1.0776x over previous
#include <cuda_runtime.h>
#include <math.h>
#include <stdint.h>

#define NNODE 512
#define MEMD  512
#define NIOU  1536
#define NCOMB 2048
#define NPAD  513

// Scratch state (device globals: allocation-free rule)
__device__ float g_xiouf[2 * NNODE * NCOMB];  // [xiou(1536) | xf(512)] per node, biases included
__device__ float g_zyA[2 * NPAD * NCOMB];     // K-slice 0 partial of h @ [W_iouh | W_fh]
__device__ float g_zyB[2 * NPAD * NCOMB];     // K-slice 1 partial
__device__ float g_c[2 * NPAD * MEMD];
__device__ float g_h[2 * NPAD * MEMD];
__device__ float g_part[16 * MEMD];           // head partial sums

__device__ __forceinline__ float sigm(float x) { return 1.f / (1.f + __expf(-x)); }
__device__ __forceinline__ float4 ld4(const float* p) { return *(const float4*)p; }
__device__ __forceinline__ float4 f4add(float4 a, float4 b) {
    return make_float4(a.x + b.x, a.y + b.y, a.z + b.z, a.w + b.w);
}
__device__ __forceinline__ uint32_t to_tf32(float x) {
    uint32_t r; asm("cvt.rna.tf32.f32 %0, %1;" : "=r"(r) : "f"(x)); return r;
}
__device__ __forceinline__ uint4 cvt4(float4 v) {
    uint4 r; r.x = to_tf32(v.x); r.y = to_tf32(v.y); r.z = to_tf32(v.z); r.w = to_tf32(v.w);
    return r;
}
__device__ __forceinline__ void mma_tf32(float d[4], const uint32_t a[4], const uint32_t b[2]) {
    asm volatile(
        "mma.sync.aligned.m16n8k8.row.col.f32.tf32.tf32.f32 "
        "{%0,%1,%2,%3}, {%4,%5,%6,%7}, {%8,%9}, {%0,%1,%2,%3};"
        : "+f"(d[0]), "+f"(d[1]), "+f"(d[2]), "+f"(d[3])
        : "r"(a[0]), "r"(a[1]), "r"(a[2]), "r"(a[3]), "r"(b[0]), "r"(b[1]));
}

// Precompute tf32 GEMM: 32(M)x64(N)xK512 block tile, BK=32, 256 threads (8 warps,
// 16x16 warp tiles), double-buffered smem, conflict-free strides (40/72 = 8 mod 32).
// C[m] = emb[tok[m]] @ [W_ioux|W_fx] + [b_ioux|b_fx]  -> g_xiouf  (m over 1024 rows)
__global__ __launch_bounds__(256) void k_pre(
    const float* __restrict__ emb, const int* __restrict__ linp, const int* __restrict__ rinp,
    const float* __restrict__ W0, const float* __restrict__ W1,
    const float* __restrict__ b0, const float* __restrict__ b1)
{
    __shared__ uint32_t As[2][32][40];
    __shared__ uint32_t Bs[2][32][72];

    const int tid = threadIdx.x;
    const int n0 = blockIdx.x * 64;
    const int m0 = blockIdx.y * 32;

    const int arow = tid >> 3;
    const int acol = (tid & 7) << 2;
    const int brow = tid >> 4;
    const int bc4  = (tid & 15) << 2;

    const float* aptr;
    {
        int gm = m0 + arow;
        int tok = (gm < NNODE) ? linp[gm] : rinp[gm - NNODE];
        aptr = emb + (size_t)tok * MEMD + acol;
    }

    const float* Bsrc; int bld; const float* bias;
    if (n0 < NIOU) { Bsrc = W0 + n0;          bld = NIOU; bias = b0 + n0; }
    else           { Bsrc = W1 + (n0 - NIOU); bld = MEMD; bias = b1 + n0 - NIOU; }

    const int lane = tid & 31, wid = tid >> 5;
    const int wm = (wid & 1) * 16, wn = (wid >> 1) * 16;
    const int g = lane >> 2, tg = lane & 3;

    float acc[2][4] = {};

    *(uint4*)&As[0][arow][acol]     = cvt4(ld4(aptr));
    *(uint4*)&Bs[0][brow][bc4]      = cvt4(ld4(Bsrc + (size_t)brow * bld + bc4));
    *(uint4*)&Bs[0][brow + 16][bc4] = cvt4(ld4(Bsrc + (size_t)(brow + 16) * bld + bc4));
    __syncthreads();

    int cur = 0;
    for (int it = 0; it < 16; it++) {
        float4 an, bn0, bn1;
        if (it < 15) {
            int k0 = (it + 1) * 32;
            an  = ld4(aptr + k0);
            bn0 = ld4(Bsrc + (size_t)(k0 + brow) * bld + bc4);
            bn1 = ld4(Bsrc + (size_t)(k0 + brow + 16) * bld + bc4);
        }
#pragma unroll
        for (int kk = 0; kk < 32; kk += 8) {
            uint32_t af[4], bf[2][2];
            af[0] = As[cur][wm + g][kk + tg];
            af[1] = As[cur][wm + g + 8][kk + tg];
            af[2] = As[cur][wm + g][kk + tg + 4];
            af[3] = As[cur][wm + g + 8][kk + tg + 4];
#pragma unroll
            for (int j = 0; j < 2; j++) {
                int bc = wn + j * 8 + g;
                bf[j][0] = Bs[cur][kk + tg][bc];
                bf[j][1] = Bs[cur][kk + tg + 4][bc];
            }
            mma_tf32(acc[0], af, bf[0]);
            mma_tf32(acc[1], af, bf[1]);
        }
        if (it < 15) {
            int nxt = cur ^ 1;
            *(uint4*)&As[nxt][arow][acol]     = cvt4(an);
            *(uint4*)&Bs[nxt][brow][bc4]      = cvt4(bn0);
            *(uint4*)&Bs[nxt][brow + 16][bc4] = cvt4(bn1);
            __syncthreads();
            cur = nxt;
        }
    }

#pragma unroll
    for (int j = 0; j < 2; j++) {
        int colin = wn + j * 8 + 2 * tg;
#pragma unroll
        for (int r = 0; r < 2; r++) {
            int mrow = m0 + wm + g + r * 8;
            float2 v = make_float2(acc[j][2 * r], acc[j][2 * r + 1]);
            v.x += bias[colin]; v.y += bias[colin + 1];
            *(float2*)(g_xiouf + (size_t)mrow * NCOMB + n0 + colin) = v;
        }
    }
}

// Level GEMM with split-K=2: partial[s][j] = g_h[t][j] @ [W_iouh|W_fh] over K slice s*256..+256.
// blockIdx.y = mtile*2 + s.  Partials go to g_zyA (s=0) / g_zyB (s=1); k_update sums them.
__global__ __launch_bounds__(256) void k_lvl(
    const float* __restrict__ Wiouh, const float* __restrict__ Wfh, int j0, int P)
{
    __shared__ uint32_t As[2][32][40];
    __shared__ uint32_t Bs[2][32][72];

    const int tid = threadIdx.x;
    const int n0 = blockIdx.x * 64;
    const int mt = blockIdx.y >> 1;
    const int s  = blockIdx.y & 1;
    const int t  = blockIdx.z;
    const int kbase = s * 256;
    const int m0 = mt * 32;

    const int arow = tid >> 3;
    const int acol = (tid & 7) << 2;
    const int brow = tid >> 4;
    const int bc4  = (tid & 15) << 2;

    const int gm = m0 + arow;
    const bool avalid = (gm < P);
    const float* aptr = g_h + (size_t)(t * NPAD + j0 + (avalid ? gm : 0)) * MEMD + kbase + acol;

    const float* Bsrc; int bld;
    if (n0 < NIOU) { Bsrc = Wiouh + n0;          bld = NIOU; }
    else           { Bsrc = Wfh + (n0 - NIOU);   bld = MEMD; }
    Bsrc += (size_t)kbase * bld;

    const int lane = tid & 31, wid = tid >> 5;
    const int wm = (wid & 1) * 16, wn = (wid >> 1) * 16;
    const int g = lane >> 2, tg = lane & 3;

    float acc[2][4] = {};

    {
        float4 av = avalid ? ld4(aptr) : make_float4(0.f, 0.f, 0.f, 0.f);
        *(uint4*)&As[0][arow][acol]     = cvt4(av);
        *(uint4*)&Bs[0][brow][bc4]      = cvt4(ld4(Bsrc + (size_t)brow * bld + bc4));
        *(uint4*)&Bs[0][brow + 16][bc4] = cvt4(ld4(Bsrc + (size_t)(brow + 16) * bld + bc4));
    }
    __syncthreads();

    int cur = 0;
    for (int it = 0; it < 8; it++) {
        float4 an, bn0, bn1;
        if (it < 7) {
            int k0 = (it + 1) * 32;
            an  = avalid ? ld4(aptr + k0) : make_float4(0.f, 0.f, 0.f, 0.f);
            bn0 = ld4(Bsrc + (size_t)(k0 + brow) * bld + bc4);
            bn1 = ld4(Bsrc + (size_t)(k0 + brow + 16) * bld + bc4);
        }
#pragma unroll
        for (int kk = 0; kk < 32; kk += 8) {
            uint32_t af[4], bf[2][2];
            af[0] = As[cur][wm + g][kk + tg];
            af[1] = As[cur][wm + g + 8][kk + tg];
            af[2] = As[cur][wm + g][kk + tg + 4];
            af[3] = As[cur][wm + g + 8][kk + tg + 4];
#pragma unroll
            for (int j = 0; j < 2; j++) {
                int bc = wn + j * 8 + g;
                bf[j][0] = Bs[cur][kk + tg][bc];
                bf[j][1] = Bs[cur][kk + tg + 4][bc];
            }
            mma_tf32(acc[0], af, bf[0]);
            mma_tf32(acc[1], af, bf[1]);
        }
        if (it < 7) {
            int nxt = cur ^ 1;
            *(uint4*)&As[nxt][arow][acol]     = cvt4(an);
            *(uint4*)&Bs[nxt][brow][bc4]      = cvt4(bn0);
            *(uint4*)&Bs[nxt][brow + 16][bc4] = cvt4(bn1);
            __syncthreads();
            cur = nxt;
        }
    }

    float* zout = s ? g_zyB : g_zyA;
#pragma unroll
    for (int j = 0; j < 2; j++) {
        int colin = wn + j * 8 + 2 * tg;
#pragma unroll
        for (int r = 0; r < 2; r++) {
            int mrow = m0 + wm + g + r * 8;
            if (mrow < P) {
                float2 v = make_float2(acc[j][2 * r], acc[j][2 * r + 1]);
                *(float2*)(zout + (size_t)(t * NPAD + j0 + mrow) * NCOMB + n0 + colin) = v;
            }
        }
    }
}

// Per-node gate math for one level. One block per (node, tree), 128 thr x 4 dims.
// Sums the two split-K partials; pad children (c==NNODE) contribute exact zeros.
__global__ __launch_bounds__(128) void k_update(
    const int* __restrict__ lch, const int* __restrict__ rch,
    const float* __restrict__ biouh, const float* __restrict__ bfh, int j0)
{
    const int t = blockIdx.y;
    const int j = j0 + blockIdx.x;
    const int* ch = (t ? rch : lch) + j * 4;
    const int d = threadIdx.x << 2;

    const float* x = g_xiouf + (size_t)(t * NNODE + j) * NCOMB;

    float4 Zi = make_float4(0.f, 0.f, 0.f, 0.f);
    float4 Zo = Zi, Zu = Zi;
    float4 Y[4], Cc[4];
#pragma unroll
    for (int q = 0; q < 4; q++) {
        int c = ch[q];
        if (c < NNODE) {
            size_t zoff = (size_t)(t * NPAD + c) * NCOMB;
            const float* zA = g_zyA + zoff;
            const float* zB = g_zyB + zoff;
            Zi = f4add(Zi, f4add(ld4(zA + d),        ld4(zB + d)));
            Zo = f4add(Zo, f4add(ld4(zA + 512 + d),  ld4(zB + 512 + d)));
            Zu = f4add(Zu, f4add(ld4(zA + 1024 + d), ld4(zB + 1024 + d)));
            Y[q]  = f4add(ld4(zA + 1536 + d), ld4(zB + 1536 + d));
            Cc[q] = ld4(g_c + (size_t)(t * NPAD + c) * MEMD + d);
        } else {
            Y[q] = Cc[q] = make_float4(0.f, 0.f, 0.f, 0.f);
        }
    }

    float4 Xi = ld4(x + d), Xo = ld4(x + 512 + d), Xu = ld4(x + 1024 + d), Xf = ld4(x + 1536 + d);
    float4 Bi = ld4(biouh + d), Bo = ld4(biouh + 512 + d), Bu = ld4(biouh + 1024 + d), Bf = ld4(bfh + d);

    float4 Oc, Oh;
#define DO(C) { \
    float ig = sigm(Xi.C + Zi.C + Bi.C); \
    float og = sigm(Xo.C + Zo.C + Bo.C); \
    float ug = tanhf(Xu.C + Zu.C + Bu.C); \
    float fb = Xf.C + Bf.C; \
    float c  = ig * ug + sigm(Y[0].C + fb) * Cc[0].C + sigm(Y[1].C + fb) * Cc[1].C \
                       + sigm(Y[2].C + fb) * Cc[2].C + sigm(Y[3].C + fb) * Cc[3].C; \
    Oc.C = c; Oh.C = og * tanhf(c); }
    DO(x) DO(y) DO(z) DO(w)
#undef DO

    *(float4*)(g_c + (size_t)(t * NPAD + j) * MEMD + d) = Oc;
    *(float4*)(g_h + (size_t)(t * NPAD + j) * MEMD + d) = Oh;
}

// Head part 1: vec = [lc*rc | |lc-rc|] (1024), partial hid pre-acts over d-slices.
__global__ __launch_bounds__(512) void k_head1(const float* __restrict__ Wh)
{
    __shared__ float vec_s[64];
    const int b = blockIdx.x, d0 = b * 64, tid = threadIdx.x;
    const float* lc = g_c + (size_t)(NNODE - 1) * MEMD;
    const float* rc = g_c + (size_t)(NPAD + NNODE - 1) * MEMD;
    if (tid < 64) {
        int dd = d0 + tid;
        vec_s[tid] = (dd < 512) ? lc[dd] * rc[dd] : fabsf(lc[dd - 512] - rc[dd - 512]);
    }
    __syncthreads();
    float acc = 0.f;
#pragma unroll 8
    for (int dd = 0; dd < 64; dd++)
        acc += vec_s[dd] * Wh[(size_t)(d0 + dd) * 512 + tid];
    g_part[b * 512 + tid] = acc;
}

// Head part 2: hid = sigmoid(.+bh); logits = hid@Wp+bp; log_softmax -> out[5]
__global__ __launch_bounds__(512) void k_head2(
    const float* __restrict__ bh, const float* __restrict__ Wp,
    const float* __restrict__ bp, float* __restrict__ out)
{
    __shared__ float hid[512];
    __shared__ float logit[5];
    const int tid = threadIdx.x;
    float a = 0.f;
#pragma unroll
    for (int b = 0; b < 16; b++) a += g_part[b * 512 + tid];
    hid[tid] = sigm(a + bh[tid]);
    __syncthreads();
    if (tid < 160) {
        int c = tid / 32, lane = tid & 31;
        float s = 0.f;
        for (int o = lane; o < 512; o += 32) s += hid[o] * Wp[o * 5 + c];
#pragma unroll
        for (int off = 16; off; off >>= 1) s += __shfl_down_sync(0xffffffffu, s, off);
        if (lane == 0) logit[c] = s + bp[c];
    }
    __syncthreads();
    if (tid == 0) {
        float m = logit[0];
#pragma unroll
        for (int c = 1; c < 5; c++) m = fmaxf(m, logit[c]);
        float se = 0.f;
#pragma unroll
        for (int c = 0; c < 5; c++) se += expf(logit[c] - m);
        float lse = m + logf(se);
#pragma unroll
        for (int c = 0; c < 5; c++) out[c] = logit[c] - lse;
    }
}

extern "C" void kernel_launch(void* const* d_in, const int* in_sizes, int n_in,
                              void* d_out, int out_size)
{
    const int*   linp  = (const int*)d_in[0];
    const int*   rinp  = (const int*)d_in[1];
    const int*   lch   = (const int*)d_in[2];
    const int*   rch   = (const int*)d_in[3];
    const float* emb   = (const float*)d_in[4];
    const float* Wioux = (const float*)d_in[5];
    const float* bioux = (const float*)d_in[6];
    const float* Wiouh = (const float*)d_in[7];
    const float* biouh = (const float*)d_in[8];
    const float* Wfx   = (const float*)d_in[9];
    const float* bfx   = (const float*)d_in[10];
    const float* Wfh   = (const float*)d_in[11];
    const float* bfh   = (const float*)d_in[12];
    const float* Wh    = (const float*)d_in[13];
    const float* bh    = (const float*)d_in[14];
    const float* Wp    = (const float*)d_in[15];
    const float* bp    = (const float*)d_in[16];
    float* out = (float*)d_out;

    // Precompute x-projections for both trees (M=1024 rows, 32-row tiles).
    k_pre<<<dim3(32, 32, 1), 256>>>(emb, linp, rinp, Wioux, Wfx, bioux, bfx);

    // Complete 4-ary tree levels in scan order (j-space, deepest first).
    static const int j0s[6] = {0, 171, 427, 491, 507, 511};
    static const int cnt[6] = {171, 256, 64, 16, 4, 1};
    for (int l = 0; l < 6; l++) {
        k_update<<<dim3(cnt[l], 2), 128>>>(lch, rch, biouh, bfh, j0s[l]);
        if (l < 5) {
            int mt = (cnt[l] + 31) / 32;
            k_lvl<<<dim3(32, mt * 2, 2), 256>>>(Wiouh, Wfh, j0s[l], cnt[l]);
        }
    }
    k_head1<<<16, 512>>>(Wh);
    k_head2<<<1, 512>>>(bh, Wp, bp, out);
}

// round 10
// speedup vs baseline: 1.1497x; 1.0669x over previous
#include <cuda_runtime.h>
#include <math.h>
#include <stdint.h>

#define NNODE 512
#define MEMD  512
#define NIOU  1536
#define NCOMB 2048
#define NPAD  513

// Scratch state (device globals: allocation-free rule)
__device__ float g_xiouf[2 * NNODE * NCOMB];  // [xiou(1536) | xf(512)] per node, biases included
__device__ float g_zyA[2 * NPAD * NCOMB];     // K-slice 0 partial of h @ [W_iouh | W_fh]
__device__ float g_zyB[2 * NPAD * NCOMB];     // K-slice 1 partial
__device__ float g_c[2 * NPAD * MEMD];
__device__ float g_h[2 * NPAD * MEMD];
__device__ float g_part[16 * MEMD];           // head partial sums

__device__ __forceinline__ float sigm(float x) { return 1.f / (1.f + __expf(-x)); }
__device__ __forceinline__ float4 ld4(const float* p) { return *(const float4*)p; }
__device__ __forceinline__ float4 f4add(float4 a, float4 b) {
    return make_float4(a.x + b.x, a.y + b.y, a.z + b.z, a.w + b.w);
}
__device__ __forceinline__ uint32_t to_tf32(float x) {
    uint32_t r; asm("cvt.rna.tf32.f32 %0, %1;" : "=r"(r) : "f"(x)); return r;
}
__device__ __forceinline__ uint4 cvt4(float4 v) {
    uint4 r; r.x = to_tf32(v.x); r.y = to_tf32(v.y); r.z = to_tf32(v.z); r.w = to_tf32(v.w);
    return r;
}
__device__ __forceinline__ void mma_tf32(float d[4], const uint32_t a[4], const uint32_t b[2]) {
    asm volatile(
        "mma.sync.aligned.m16n8k8.row.col.f32.tf32.tf32.f32 "
        "{%0,%1,%2,%3}, {%4,%5,%6,%7}, {%8,%9}, {%0,%1,%2,%3};"
        : "+f"(d[0]), "+f"(d[1]), "+f"(d[2]), "+f"(d[3])
        : "r"(a[0]), "r"(a[1]), "r"(a[2]), "r"(a[3]), "r"(b[0]), "r"(b[1]));
}

// Precompute tf32 GEMM: 32(M)x64(N)xK512 block tile, BK=32, 256 threads (8 warps,
// 16x16 warp tiles), double-buffered smem, conflict-free strides (40/72 = 8 mod 32).
// C[m] = emb[tok[m]] @ [W_ioux|W_fx] + [b_ioux|b_fx]  -> g_xiouf  (m over 1024 rows)
__global__ __launch_bounds__(256) void k_pre(
    const float* __restrict__ emb, const int* __restrict__ linp, const int* __restrict__ rinp,
    const float* __restrict__ W0, const float* __restrict__ W1,
    const float* __restrict__ b0, const float* __restrict__ b1)
{
    __shared__ uint32_t As[2][32][40];
    __shared__ uint32_t Bs[2][32][72];

    const int tid = threadIdx.x;
    const int n0 = blockIdx.x * 64;
    const int m0 = blockIdx.y * 32;

    const int arow = tid >> 3;
    const int acol = (tid & 7) << 2;
    const int brow = tid >> 4;
    const int bc4  = (tid & 15) << 2;

    const float* aptr;
    {
        int gm = m0 + arow;
        int tok = (gm < NNODE) ? linp[gm] : rinp[gm - NNODE];
        aptr = emb + (size_t)tok * MEMD + acol;
    }

    const float* Bsrc; int bld; const float* bias;
    if (n0 < NIOU) { Bsrc = W0 + n0;          bld = NIOU; bias = b0 + n0; }
    else           { Bsrc = W1 + (n0 - NIOU); bld = MEMD; bias = b1 + n0 - NIOU; }

    const int lane = tid & 31, wid = tid >> 5;
    const int wm = (wid & 1) * 16, wn = (wid >> 1) * 16;
    const int g = lane >> 2, tg = lane & 3;

    float acc[2][4] = {};

    *(uint4*)&As[0][arow][acol]     = cvt4(ld4(aptr));
    *(uint4*)&Bs[0][brow][bc4]      = cvt4(ld4(Bsrc + (size_t)brow * bld + bc4));
    *(uint4*)&Bs[0][brow + 16][bc4] = cvt4(ld4(Bsrc + (size_t)(brow + 16) * bld + bc4));
    __syncthreads();

    int cur = 0;
    for (int it = 0; it < 16; it++) {
        float4 an, bn0, bn1;
        if (it < 15) {
            int k0 = (it + 1) * 32;
            an  = ld4(aptr + k0);
            bn0 = ld4(Bsrc + (size_t)(k0 + brow) * bld + bc4);
            bn1 = ld4(Bsrc + (size_t)(k0 + brow + 16) * bld + bc4);
        }
#pragma unroll
        for (int kk = 0; kk < 32; kk += 8) {
            uint32_t af[4], bf[2][2];
            af[0] = As[cur][wm + g][kk + tg];
            af[1] = As[cur][wm + g + 8][kk + tg];
            af[2] = As[cur][wm + g][kk + tg + 4];
            af[3] = As[cur][wm + g + 8][kk + tg + 4];
#pragma unroll
            for (int j = 0; j < 2; j++) {
                int bc = wn + j * 8 + g;
                bf[j][0] = Bs[cur][kk + tg][bc];
                bf[j][1] = Bs[cur][kk + tg + 4][bc];
            }
            mma_tf32(acc[0], af, bf[0]);
            mma_tf32(acc[1], af, bf[1]);
        }
        if (it < 15) {
            int nxt = cur ^ 1;
            *(uint4*)&As[nxt][arow][acol]     = cvt4(an);
            *(uint4*)&Bs[nxt][brow][bc4]      = cvt4(bn0);
            *(uint4*)&Bs[nxt][brow + 16][bc4] = cvt4(bn1);
            __syncthreads();
            cur = nxt;
        }
    }

#pragma unroll
    for (int j = 0; j < 2; j++) {
        int colin = wn + j * 8 + 2 * tg;
#pragma unroll
        for (int r = 0; r < 2; r++) {
            int mrow = m0 + wm + g + r * 8;
            float2 v = make_float2(acc[j][2 * r], acc[j][2 * r + 1]);
            v.x += bias[colin]; v.y += bias[colin + 1];
            *(float2*)(g_xiouf + (size_t)mrow * NCOMB + n0 + colin) = v;
        }
    }
}

// Level GEMM with split-K=2 + PDL prologue: B-weight tile 0 is staged into smem
// BEFORE cudaGridDependencySynchronize (weights are kernel inputs, independent of
// the predecessor). A (g_h, written by predecessor k_update) is loaded after.
__global__ __launch_bounds__(256) void k_lvl(
    const float* __restrict__ Wiouh, const float* __restrict__ Wfh, int j0, int P)
{
    __shared__ uint32_t As[2][32][40];
    __shared__ uint32_t Bs[2][32][72];

    const int tid = threadIdx.x;
    const int n0 = blockIdx.x * 64;
    const int mt = blockIdx.y >> 1;
    const int s  = blockIdx.y & 1;
    const int t  = blockIdx.z;
    const int kbase = s * 256;
    const int m0 = mt * 32;

    const int arow = tid >> 3;
    const int acol = (tid & 7) << 2;
    const int brow = tid >> 4;
    const int bc4  = (tid & 15) << 2;

    const float* Bsrc; int bld;
    if (n0 < NIOU) { Bsrc = Wiouh + n0;          bld = NIOU; }
    else           { Bsrc = Wfh + (n0 - NIOU);   bld = MEMD; }
    Bsrc += (size_t)kbase * bld;

    // ---- PDL prologue: weights only ----
    *(uint4*)&Bs[0][brow][bc4]      = cvt4(ld4(Bsrc + (size_t)brow * bld + bc4));
    *(uint4*)&Bs[0][brow + 16][bc4] = cvt4(ld4(Bsrc + (size_t)(brow + 16) * bld + bc4));

    cudaGridDependencySynchronize();

    const int gm = m0 + arow;
    const bool avalid = (gm < P);
    const float* aptr = g_h + (size_t)(t * NPAD + j0 + (avalid ? gm : 0)) * MEMD + kbase + acol;

    {
        float4 av = avalid ? ld4(aptr) : make_float4(0.f, 0.f, 0.f, 0.f);
        *(uint4*)&As[0][arow][acol] = cvt4(av);
    }

    const int lane = tid & 31, wid = tid >> 5;
    const int wm = (wid & 1) * 16, wn = (wid >> 1) * 16;
    const int g = lane >> 2, tg = lane & 3;

    float acc[2][4] = {};
    __syncthreads();

    int cur = 0;
    for (int it = 0; it < 8; it++) {
        float4 an, bn0, bn1;
        if (it < 7) {
            int k0 = (it + 1) * 32;
            an  = avalid ? ld4(aptr + k0) : make_float4(0.f, 0.f, 0.f, 0.f);
            bn0 = ld4(Bsrc + (size_t)(k0 + brow) * bld + bc4);
            bn1 = ld4(Bsrc + (size_t)(k0 + brow + 16) * bld + bc4);
        }
#pragma unroll
        for (int kk = 0; kk < 32; kk += 8) {
            uint32_t af[4], bf[2][2];
            af[0] = As[cur][wm + g][kk + tg];
            af[1] = As[cur][wm + g + 8][kk + tg];
            af[2] = As[cur][wm + g][kk + tg + 4];
            af[3] = As[cur][wm + g + 8][kk + tg + 4];
#pragma unroll
            for (int j = 0; j < 2; j++) {
                int bc = wn + j * 8 + g;
                bf[j][0] = Bs[cur][kk + tg][bc];
                bf[j][1] = Bs[cur][kk + tg + 4][bc];
            }
            mma_tf32(acc[0], af, bf[0]);
            mma_tf32(acc[1], af, bf[1]);
        }
        if (it < 7) {
            int nxt = cur ^ 1;
            *(uint4*)&As[nxt][arow][acol]     = cvt4(an);
            *(uint4*)&Bs[nxt][brow][bc4]      = cvt4(bn0);
            *(uint4*)&Bs[nxt][brow + 16][bc4] = cvt4(bn1);
            __syncthreads();
            cur = nxt;
        }
    }

    float* zout = s ? g_zyB : g_zyA;
#pragma unroll
    for (int j = 0; j < 2; j++) {
        int colin = wn + j * 8 + 2 * tg;
#pragma unroll
        for (int r = 0; r < 2; r++) {
            int mrow = m0 + wm + g + r * 8;
            if (mrow < P) {
                float2 v = make_float2(acc[j][2 * r], acc[j][2 * r + 1]);
                *(float2*)(zout + (size_t)(t * NPAD + j0 + mrow) * NCOMB + n0 + colin) = v;
            }
        }
    }
}

// Per-node gate math for one level (PDL: indices + biases loaded pre-sync).
__global__ __launch_bounds__(128) void k_update(
    const int* __restrict__ lch, const int* __restrict__ rch,
    const float* __restrict__ biouh, const float* __restrict__ bfh, int j0)
{
    const int t = blockIdx.y;
    const int j = j0 + blockIdx.x;
    const int* ch = (t ? rch : lch) + j * 4;
    const int d = threadIdx.x << 2;

    // ---- PDL prologue: kernel inputs only ----
    const int c0i = ch[0], c1i = ch[1], c2i = ch[2], c3i = ch[3];
    float4 Bi = ld4(biouh + d), Bo = ld4(biouh + 512 + d), Bu = ld4(biouh + 1024 + d), Bf = ld4(bfh + d);

    cudaGridDependencySynchronize();

    const int chl[4] = {c0i, c1i, c2i, c3i};
    const float* x = g_xiouf + (size_t)(t * NNODE + j) * NCOMB;

    float4 Zi = make_float4(0.f, 0.f, 0.f, 0.f);
    float4 Zo = Zi, Zu = Zi;
    float4 Y[4], Cc[4];
#pragma unroll
    for (int q = 0; q < 4; q++) {
        int c = chl[q];
        if (c < NNODE) {
            size_t zoff = (size_t)(t * NPAD + c) * NCOMB;
            const float* zA = g_zyA + zoff;
            const float* zB = g_zyB + zoff;
            Zi = f4add(Zi, f4add(ld4(zA + d),        ld4(zB + d)));
            Zo = f4add(Zo, f4add(ld4(zA + 512 + d),  ld4(zB + 512 + d)));
            Zu = f4add(Zu, f4add(ld4(zA + 1024 + d), ld4(zB + 1024 + d)));
            Y[q]  = f4add(ld4(zA + 1536 + d), ld4(zB + 1536 + d));
            Cc[q] = ld4(g_c + (size_t)(t * NPAD + c) * MEMD + d);
        } else {
            Y[q] = Cc[q] = make_float4(0.f, 0.f, 0.f, 0.f);
        }
    }

    float4 Xi = ld4(x + d), Xo = ld4(x + 512 + d), Xu = ld4(x + 1024 + d), Xf = ld4(x + 1536 + d);

    float4 Oc, Oh;
#define DO(C) { \
    float ig = sigm(Xi.C + Zi.C + Bi.C); \
    float og = sigm(Xo.C + Zo.C + Bo.C); \
    float ug = tanhf(Xu.C + Zu.C + Bu.C); \
    float fb = Xf.C + Bf.C; \
    float c  = ig * ug + sigm(Y[0].C + fb) * Cc[0].C + sigm(Y[1].C + fb) * Cc[1].C \
                       + sigm(Y[2].C + fb) * Cc[2].C + sigm(Y[3].C + fb) * Cc[3].C; \
    Oc.C = c; Oh.C = og * tanhf(c); }
    DO(x) DO(y) DO(z) DO(w)
#undef DO

    *(float4*)(g_c + (size_t)(t * NPAD + j) * MEMD + d) = Oc;
    *(float4*)(g_h + (size_t)(t * NPAD + j) * MEMD + d) = Oh;
}

// Fused root-update + head part 1. Each of 16 blocks recomputes the 64-dim slice
// of the root cell state it needs (redundant x2 across blocks; trivial cost),
// then forms vec = [lc*rc | |lc-rc|] slice and partial hid pre-activations.
__global__ __launch_bounds__(512) void k_head1f(
    const int* __restrict__ lch, const int* __restrict__ rch,
    const float* __restrict__ biouh, const float* __restrict__ bfh,
    const float* __restrict__ Wh)
{
    __shared__ float sh_c[2][64];
    __shared__ float vec_s[64];
    const int b = blockIdx.x, tid = threadIdx.x;
    const int s0 = (b & 7) * 64;

    cudaGridDependencySynchronize();

    if (tid < 128) {
        int t = tid >> 6;
        int i = tid & 63;
        int dd = s0 + i;
        const int* ch = (t ? rch : lch) + 511 * 4;
        const float* x = g_xiouf + (size_t)(t * NNODE + 511) * NCOMB;
        float zi = 0.f, zo = 0.f, zu = 0.f;
        float y[4], cc[4];
#pragma unroll
        for (int q = 0; q < 4; q++) {
            int c = ch[q];  // root children are real nodes
            size_t zoff = (size_t)(t * NPAD + c) * NCOMB;
            zi += g_zyA[zoff + dd] + g_zyB[zoff + dd];
            zo += g_zyA[zoff + 512 + dd] + g_zyB[zoff + 512 + dd];
            zu += g_zyA[zoff + 1024 + dd] + g_zyB[zoff + 1024 + dd];
            y[q]  = g_zyA[zoff + 1536 + dd] + g_zyB[zoff + 1536 + dd];
            cc[q] = g_c[(size_t)(t * NPAD + c) * MEMD + dd];
        }
        float ig = sigm(x[dd] + zi + biouh[dd]);
        float ug = tanhf(x[1024 + dd] + zu + biouh[1024 + dd]);
        float fb = x[1536 + dd] + bfh[dd];
        float cval = ig * ug + sigm(y[0] + fb) * cc[0] + sigm(y[1] + fb) * cc[1]
                             + sigm(y[2] + fb) * cc[2] + sigm(y[3] + fb) * cc[3];
        (void)zo;
        sh_c[t][i] = cval;
    }
    __syncthreads();
    if (tid < 64) {
        float l = sh_c[0][tid], r = sh_c[1][tid];
        vec_s[tid] = (b < 8) ? l * r : fabsf(l - r);
    }
    __syncthreads();
    float acc = 0.f;
    int d0 = b * 64;
#pragma unroll 8
    for (int dd = 0; dd < 64; dd++)
        acc += vec_s[dd] * Wh[(size_t)(d0 + dd) * 512 + tid];
    g_part[b * 512 + tid] = acc;
}

// Head part 2: hid = sigmoid(.+bh); logits = hid@Wp+bp; log_softmax -> out[5]
__global__ __launch_bounds__(512) void k_head2(
    const float* __restrict__ bh, const float* __restrict__ Wp,
    const float* __restrict__ bp, float* __restrict__ out)
{
    __shared__ float hid[512];
    __shared__ float logit[5];
    const int tid = threadIdx.x;

    cudaGridDependencySynchronize();

    float a = 0.f;
#pragma unroll
    for (int b = 0; b < 16; b++) a += g_part[b * 512 + tid];
    hid[tid] = sigm(a + bh[tid]);
    __syncthreads();
    if (tid < 160) {
        int c = tid / 32, lane = tid & 31;
        float s = 0.f;
        for (int o = lane; o < 512; o += 32) s += hid[o] * Wp[o * 5 + c];
#pragma unroll
        for (int off = 16; off; off >>= 1) s += __shfl_down_sync(0xffffffffu, s, off);
        if (lane == 0) logit[c] = s + bp[c];
    }
    __syncthreads();
    if (tid == 0) {
        float m = logit[0];
#pragma unroll
        for (int c = 1; c < 5; c++) m = fmaxf(m, logit[c]);
        float se = 0.f;
#pragma unroll
        for (int c = 0; c < 5; c++) se += expf(logit[c] - m);
        float lse = m + logf(se);
#pragma unroll
        for (int c = 0; c < 5; c++) out[c] = logit[c] - lse;
    }
}

extern "C" void kernel_launch(void* const* d_in, const int* in_sizes, int n_in,
                              void* d_out, int out_size)
{
    const int*   linp  = (const int*)d_in[0];
    const int*   rinp  = (const int*)d_in[1];
    const int*   lch   = (const int*)d_in[2];
    const int*   rch   = (const int*)d_in[3];
    const float* emb   = (const float*)d_in[4];
    const float* Wioux = (const float*)d_in[5];
    const float* bioux = (const float*)d_in[6];
    const float* Wiouh = (const float*)d_in[7];
    const float* biouh = (const float*)d_in[8];
    const float* Wfx   = (const float*)d_in[9];
    const float* bfx   = (const float*)d_in[10];
    const float* Wfh   = (const float*)d_in[11];
    const float* bfh   = (const float*)d_in[12];
    const float* Wh    = (const float*)d_in[13];
    const float* bh    = (const float*)d_in[14];
    const float* Wp    = (const float*)d_in[15];
    const float* bp    = (const float*)d_in[16];
    float* out = (float*)d_out;

    // First launch: normal (its predecessor is outside our chain).
    k_pre<<<dim3(32, 32, 1), 256>>>(emb, linp, rinp, Wioux, Wfx, bioux, bfx);

    // All subsequent launches: PDL so each kernel's launch + input-only prologue
    // overlaps the predecessor's tail.
    cudaLaunchAttribute attr;
    attr.id = cudaLaunchAttributeProgrammaticStreamSerialization;
    attr.val.programmaticStreamSerializationAllowed = 1;
    cudaLaunchConfig_t cfg = {};
    cfg.attrs = &attr;
    cfg.numAttrs = 1;
    cfg.stream = 0;

    static const int j0s[5] = {0, 171, 427, 491, 507};
    static const int cnt[5] = {171, 256, 64, 16, 4};
    for (int l = 0; l < 5; l++) {
        cfg.gridDim = dim3(cnt[l], 2, 1);
        cfg.blockDim = dim3(128, 1, 1);
        cudaLaunchKernelEx(&cfg, k_update, lch, rch, biouh, bfh, j0s[l]);

        int mt = (cnt[l] + 31) / 32;
        cfg.gridDim = dim3(32, mt * 2, 2);
        cfg.blockDim = dim3(256, 1, 1);
        cudaLaunchKernelEx(&cfg, k_lvl, Wiouh, Wfh, j0s[l], cnt[l]);
    }

    cfg.gridDim = dim3(16, 1, 1);
    cfg.blockDim = dim3(512, 1, 1);
    cudaLaunchKernelEx(&cfg, k_head1f, lch, rch, biouh, bfh, Wh);

    cfg.gridDim = dim3(1, 1, 1);
    cfg.blockDim = dim3(512, 1, 1);
    cudaLaunchKernelEx(&cfg, k_head2, bh, Wp, bp, out);
}